// round 12
// baseline (speedup 1.0000x reference)
#include <cuda_runtime.h>
#include <cstdint>
#include <math.h>

#define B_  4
#define S_  2048
#define D_  768
#define H_  12
#define E_  64
#define BS_ (B_ * S_)   // 8192

// Scratch (static device globals: allocation-free per harness rules)
__device__ float g_q[(size_t)B_ * H_ * S_ * E_];
__device__ float g_k[(size_t)B_ * H_ * S_ * E_];
__device__ float g_v[(size_t)B_ * H_ * S_ * E_];
__device__ float g_z[(size_t)BS_ * D_];
__device__ float g_wt [(size_t)H_ * 192 * D_];   // [h][3*64 (Q|K|V rows)][768] K-major, tf32-rounded
__device__ float g_wot[(size_t)D_ * D_];         // Wo^T [768][768] K-major, tf32-rounded

// ---------------------------------------------------------------------------
__device__ __forceinline__ unsigned tf32cvt(float f) {
    unsigned u;
    asm("cvt.rna.tf32.f32 %0, %1;" : "=r"(u) : "f"(f));
    return u;
}

__device__ __forceinline__ void mma8(float c[4],
                                     unsigned a0, unsigned a1, unsigned a2, unsigned a3,
                                     unsigned b0, unsigned b1) {
    asm volatile(
        "mma.sync.aligned.m16n8k8.row.col.f32.tf32.tf32.f32 "
        "{%0,%1,%2,%3}, {%4,%5,%6,%7}, {%8,%9}, {%0,%1,%2,%3};\n"
        : "+f"(c[0]), "+f"(c[1]), "+f"(c[2]), "+f"(c[3])
        : "r"(a0), "r"(a1), "r"(a2), "r"(a3), "r"(b0), "r"(b1));
}

__device__ __forceinline__ float f4get(const float4& v, int j) {
    return j == 0 ? v.x : j == 1 ? v.y : j == 2 ? v.z : v.w;
}

// ---------------------------------------------------------------------------
// Weight transposes (tiny, once per launch). [R][C] -> [C][R], tf32-rounded.
// ---------------------------------------------------------------------------
__global__ void __launch_bounds__(256) transpose_qkv(
    const float* __restrict__ WQ, const float* __restrict__ WK, const float* __restrict__ WV)
{
    __shared__ float tile[32][33];
    int z = blockIdx.z, h = z / 3, m = z % 3;
    const float* src = (m == 0 ? WQ : m == 1 ? WK : WV) + (size_t)h * D_ * E_;  // [768][64]
    float* dst = g_wt + ((size_t)h * 192 + m * 64) * D_;                        // [64][768]
    int r0 = blockIdx.x * 32, c0 = blockIdx.y * 32;
    int tx = threadIdx.x & 31, ty = threadIdx.x >> 5;
    #pragma unroll
    for (int i = 0; i < 4; ++i)
        tile[ty + 8 * i][tx] = src[(size_t)(r0 + ty + 8 * i) * E_ + c0 + tx];
    __syncthreads();
    #pragma unroll
    for (int i = 0; i < 4; ++i)
        dst[(size_t)(c0 + ty + 8 * i) * D_ + r0 + tx] =
            __uint_as_float(tf32cvt(tile[tx][ty + 8 * i]));
}

__global__ void __launch_bounds__(256) transpose_wo(const float* __restrict__ Wo)
{
    __shared__ float tile[32][33];
    int r0 = blockIdx.x * 32, c0 = blockIdx.y * 32;
    int tx = threadIdx.x & 31, ty = threadIdx.x >> 5;
    #pragma unroll
    for (int i = 0; i < 4; ++i)
        tile[ty + 8 * i][tx] = Wo[(size_t)(r0 + ty + 8 * i) * D_ + c0 + tx];
    __syncthreads();
    #pragma unroll
    for (int i = 0; i < 4; ++i)
        g_wot[(size_t)(c0 + ty + 8 * i) * D_ + r0 + tx] =
            __uint_as_float(tf32cvt(tile[tx][ty + 8 * i]));
}

// ---------------------------------------------------------------------------
// Fragment-packed GEMM, 128(M) x 64(N) block tile, K-tile 32, 256 thr (8 warps
// as 4m x 2n, each 32x32). Frag layouts (words):
//   A-frag(kt 0..3, mt 0..7): 128 words, logical lane L at word (L^kt)*4 .. +3
//       holding {a0,a1,a2,a3} of mma m16n8k8 row-major A.
//   B-frag(kt 0..3, nt 0..7): 64 words, lane L at (L^kt)*2 holding {b0,b1}.
// Double buffered: A at 0/4096, B at 8192/10240 words (48KB total).
// ---------------------------------------------------------------------------
#define GA_OFF(b) ((b) * 4096)
#define GB_OFF(b) (8192 + (b) * 2048)
#define G_SMEM    49152

// One K32 tile load: A from fp32 src (cvt), B from pre-tf32 K-major src.
__device__ __forceinline__ void g_load_tile(
    unsigned* sm, int buf, const float* __restrict__ Asrc, const float* __restrict__ Bsrc,
    int tid, int kb)
{
    // A: thread -> rows {arow, arow+8}, k-cols kt*8..+7  (16 elements, 4 STS.128)
    const int arb = tid >> 2, amt = arb >> 3, arm8 = arb & 7;
    const int arow = amt * 16 + arm8;
    const int akt = tid & 3;
    const float* ap = Asrc + (size_t)arow * D_ + kb + akt * 8;
    float4 fa = *reinterpret_cast<const float4*>(ap);
    float4 fb = *reinterpret_cast<const float4*>(ap + 4);
    float4 fc = *reinterpret_cast<const float4*>(ap + 8 * D_);
    float4 fd = *reinterpret_cast<const float4*>(ap + 8 * D_ + 4);
    unsigned* Af = sm + GA_OFF(buf) + (((akt << 3) + amt) << 7);
    #pragma unroll
    for (int j = 0; j < 4; ++j) {
        uint4 v = { tf32cvt(f4get(fa, j)), tf32cvt(f4get(fc, j)),
                    tf32cvt(f4get(fb, j)), tf32cvt(f4get(fd, j)) };
        int ll = (arm8 << 2) + j;
        *reinterpret_cast<uint4*>(&Af[(ll ^ akt) << 2]) = v;
    }
    // B: thread -> row bn, k-cols bkt*8..+7 (8 elements, 4 STS.64)
    const int bn = tid >> 2, bnt = bn >> 3, bkt = tid & 3;
    const float* bp = Bsrc + (size_t)bn * D_ + kb + bkt * 8;
    float4 ga = *reinterpret_cast<const float4*>(bp);
    float4 gb = *reinterpret_cast<const float4*>(bp + 4);
    unsigned* Bf = sm + GB_OFF(buf) + (((bkt << 3) + bnt) << 6);
    #pragma unroll
    for (int j = 0; j < 4; ++j) {
        uint2 v = { __float_as_uint(f4get(ga, j)), __float_as_uint(f4get(gb, j)) };
        int ll = ((bn & 7) << 2) + j;
        *reinterpret_cast<uint2*>(&Bf[(ll ^ bkt) << 1]) = v;
    }
}

__device__ __forceinline__ void g_compute(
    unsigned* sm, int buf, int wm, int wn, int lane, float acc[2][4][4])
{
    #pragma unroll
    for (int kt = 0; kt < 4; ++kt) {
        const int lx = lane ^ kt;
        uint4 a0 = *reinterpret_cast<const uint4*>(
            &sm[GA_OFF(buf) + (((kt << 3) + wm * 2    ) << 7) + (lx << 2)]);
        uint4 a1 = *reinterpret_cast<const uint4*>(
            &sm[GA_OFF(buf) + (((kt << 3) + wm * 2 + 1) << 7) + (lx << 2)]);
        #pragma unroll
        for (int nt = 0; nt < 4; ++nt) {
            uint2 b = *reinterpret_cast<const uint2*>(
                &sm[GB_OFF(buf) + (((kt << 3) + wn * 4 + nt) << 6) + (lx << 1)]);
            mma8(acc[0][nt], a0.x, a0.y, a0.z, a0.w, b.x, b.y);
            mma8(acc[1][nt], a1.x, a1.y, a1.z, a1.w, b.x, b.y);
        }
    }
}

// QKV projection: grid (64, H, 3)
__global__ void __launch_bounds__(256) qkv_frag(
    const float* __restrict__ x,
    const float* __restrict__ bQ, const float* __restrict__ bK, const float* __restrict__ bV,
    float* __restrict__ q, float* __restrict__ k, float* __restrict__ v)
{
    extern __shared__ unsigned sm[];
    const int row0 = blockIdx.x * 128;
    const int h    = blockIdx.y;
    const int m    = blockIdx.z;
    const int tid  = threadIdx.x;
    const int lane = tid & 31;
    const int wid  = tid >> 5;
    const int wm   = wid >> 1, wn = wid & 1;

    const float* Asrc = x + (size_t)row0 * D_;
    const float* Bsrc = g_wt + ((size_t)h * 192 + m * 64) * D_;
    float* out = m == 0 ? q : m == 1 ? k : v;
    const float* bias = m == 0 ? bQ : m == 1 ? bK : bV;

    float acc[2][4][4] = {};

    g_load_tile(sm, 0, Asrc, Bsrc, tid, 0);
    __syncthreads();
    for (int t = 0; t < 24; ++t) {
        if (t + 1 < 24) g_load_tile(sm, (t + 1) & 1, Asrc, Bsrc, tid, (t + 1) * 32);
        g_compute(sm, t & 1, wm, wn, lane, acc);
        __syncthreads();
    }

    #pragma unroll
    for (int mt = 0; mt < 2; ++mt) {
        #pragma unroll
        for (int rr = 0; rr < 2; ++rr) {
            int row = row0 + wm * 32 + mt * 16 + (lane >> 2) + rr * 8;
            int b_  = row / S_, s = row % S_;
            float* orow = out + ((size_t)(b_ * H_ + h) * S_ + s) * E_;
            #pragma unroll
            for (int nt = 0; nt < 4; ++nt) {
                int e = wn * 32 + nt * 8 + 2 * (lane & 3);
                orow[e    ] = acc[mt][nt][rr * 2    ] + bias[h * E_ + e];
                orow[e + 1] = acc[mt][nt][rr * 2 + 1] + bias[h * E_ + e + 1];
            }
        }
    }
}

// Output projection: grid (64, 12)
__global__ void __launch_bounds__(256) out_frag(
    const float* __restrict__ bO, float* __restrict__ out)
{
    extern __shared__ unsigned sm[];
    const int row0 = blockIdx.x * 128;
    const int n0   = blockIdx.y * 64;
    const int tid  = threadIdx.x;
    const int lane = tid & 31;
    const int wid  = tid >> 5;
    const int wm   = wid >> 1, wn = wid & 1;

    const float* Asrc = g_z + (size_t)row0 * D_;
    const float* Bsrc = g_wot + (size_t)n0 * D_;

    float acc[2][4][4] = {};

    g_load_tile(sm, 0, Asrc, Bsrc, tid, 0);
    __syncthreads();
    for (int t = 0; t < 24; ++t) {
        if (t + 1 < 24) g_load_tile(sm, (t + 1) & 1, Asrc, Bsrc, tid, (t + 1) * 32);
        g_compute(sm, t & 1, wm, wn, lane, acc);
        __syncthreads();
    }

    #pragma unroll
    for (int mt = 0; mt < 2; ++mt) {
        #pragma unroll
        for (int rr = 0; rr < 2; ++rr) {
            int row = row0 + wm * 32 + mt * 16 + (lane >> 2) + rr * 8;
            #pragma unroll
            for (int nt = 0; nt < 4; ++nt) {
                int d = n0 + wn * 32 + nt * 8 + 2 * (lane & 3);
                out[(size_t)row * D_ + d    ] = acc[mt][nt][rr * 2    ] + bO[d];
                out[(size_t)row * D_ + d + 1] = acc[mt][nt][rr * 2 + 1] + bO[d + 1];
            }
        }
    }
}

// ---------------------------------------------------------------------------
// Flash attention, fragment-packed. Block = (b,h,64-q-tile), 128 threads.
// Smem (words): Kf[0..4096) B-frags (kt 0..7 hd, nt 0..7 keys),
//               Vf[4096..8192) B-frags (kt 0..7 keys, nt 0..7 hd),
//               Pf[8192..12288) per-warp A-frags (w*1024, kt 0..7).
// Q fragments live in registers (loaded once via Kf staging).
// ---------------------------------------------------------------------------
#define AT_SMEM 49152

__global__ void __launch_bounds__(128) attn_frag()
{
    extern __shared__ unsigned sm[];
    unsigned* Kf = sm;
    unsigned* Vf = sm + 4096;
    unsigned* Pf = sm + 8192;

    const int qt  = blockIdx.x;
    const int h   = blockIdx.y;
    const int b   = blockIdx.z;
    const int tid = threadIdx.x;
    const int lane = tid & 31;
    const int w    = tid >> 5;

    const size_t bh = ((size_t)(b * H_ + h)) * S_ * E_;

    // ---- stage Q (tf32) into Kf as linear [64][64], then lift frags to regs
    #pragma unroll
    for (int i = 0; i < 8; ++i) {
        int idx = tid + i * 128;
        int r = idx >> 4, c4 = (idx & 15) * 4;
        float4 f = *reinterpret_cast<const float4*>(&g_q[bh + (size_t)(qt * 64 + r) * E_ + c4]);
        uint4 u = { tf32cvt(f.x), tf32cvt(f.y), tf32cvt(f.z), tf32cvt(f.w) };
        *reinterpret_cast<uint4*>(&Kf[r * 64 + c4]) = u;
    }
    __syncthreads();
    const int ar = w * 16 + (lane >> 2);
    unsigned qa[8][4];
    #pragma unroll
    for (int kt = 0; kt < 8; ++kt) {
        int ac = kt * 8 + (lane & 3);
        qa[kt][0] = Kf[ar * 64 + ac];
        qa[kt][1] = Kf[(ar + 8) * 64 + ac];
        qa[kt][2] = Kf[ar * 64 + ac + 4];
        qa[kt][3] = Kf[(ar + 8) * 64 + ac + 4];
    }
    __syncthreads();

    float o[8][4] = {};
    float m_[2] = { -1e30f, -1e30f };
    float l_[2] = { 0.f, 0.f };
    const float scale = 0.125f;

    unsigned* Pw = Pf + (w << 10);
    const int plt = ((lane >> 2) << 2) + (((lane & 3) & 1) << 1);  // even
    const int prr = ((lane & 3) >> 1) << 1;                        // 0 or 2

    for (int jt = 0; jt <= qt; ++jt) {
        // ---- load K tile into B-frag layout (n=key, k=headdim)
        #pragma unroll
        for (int c = 0; c < 4; ++c) {
            int ch = c * 128 + tid;
            int key = ch >> 3, e0 = (ch & 7) * 8;
            const float* kp = &g_k[bh + (size_t)(jt * 64 + key) * E_ + e0];
            float4 fa = *reinterpret_cast<const float4*>(kp);
            float4 fb = *reinterpret_cast<const float4*>(kp + 4);
            int kt = ch & 7, nt = key >> 3;
            unsigned* dst = Kf + (((kt << 3) + nt) << 6);
            #pragma unroll
            for (int j = 0; j < 4; ++j) {
                uint2 vv = { tf32cvt(f4get(fa, j)), tf32cvt(f4get(fb, j)) };
                int ll = ((key & 7) << 2) + j;
                *reinterpret_cast<uint2*>(&dst[(ll ^ (kt & 3)) << 1]) = vv;
            }
        }
        // ---- load V tile into B-frag layout (n=headdim, k=key)
        #pragma unroll
        for (int c = 0; c < 4; ++c) {
            int ch = c * 128 + tid;
            int kbi = ch >> 4, e0 = (ch & 15) * 4;
            int keyb = (kbi >> 2) * 8 + (kbi & 3);
            const float* vp = &g_v[bh + (size_t)(jt * 64 + keyb) * E_ + e0];
            float4 fa = *reinterpret_cast<const float4*>(vp);
            float4 fb = *reinterpret_cast<const float4*>(vp + 4 * E_);
            int kt = keyb >> 3, nt = e0 >> 3;
            unsigned* dst = Vf + (((kt << 3) + nt) << 6);
            #pragma unroll
            for (int j = 0; j < 4; ++j) {
                uint2 vv = { tf32cvt(f4get(fa, j)), tf32cvt(f4get(fb, j)) };
                int ll = (((e0 + j) & 7) << 2) + (keyb & 3);
                *reinterpret_cast<uint2*>(&dst[(ll ^ (kt & 3)) << 1]) = vv;
            }
        }
        __syncthreads();

        // ---- S = Q K^T
        float s[8][4] = {};
        #pragma unroll
        for (int kt = 0; kt < 8; ++kt) {
            const int lx2 = (lane ^ (kt & 3)) << 1;
            #pragma unroll
            for (int nt = 0; nt < 8; ++nt) {
                uint2 bk = *reinterpret_cast<const uint2*>(&Kf[(((kt << 3) + nt) << 6) + lx2]);
                mma8(s[nt], qa[kt][0], qa[kt][1], qa[kt][2], qa[kt][3], bk.x, bk.y);
            }
        }

        // ---- scale + causal mask + online softmax
        const int qrow0 = qt * 64 + w * 16 + (lane >> 2);
        float mnew0 = m_[0], mnew1 = m_[1];
        #pragma unroll
        for (int nt = 0; nt < 8; ++nt) {
            int col = jt * 64 + nt * 8 + 2 * (lane & 3);
            float v0 = s[nt][0] * scale;
            float v1 = s[nt][1] * scale;
            float v2 = s[nt][2] * scale;
            float v3 = s[nt][3] * scale;
            if (jt == qt) {
                if (col     > qrow0)     v0 = -1e30f;
                if (col + 1 > qrow0)     v1 = -1e30f;
                if (col     > qrow0 + 8) v2 = -1e30f;
                if (col + 1 > qrow0 + 8) v3 = -1e30f;
            }
            s[nt][0] = v0; s[nt][1] = v1; s[nt][2] = v2; s[nt][3] = v3;
            mnew0 = fmaxf(mnew0, fmaxf(v0, v1));
            mnew1 = fmaxf(mnew1, fmaxf(v2, v3));
        }
        mnew0 = fmaxf(mnew0, __shfl_xor_sync(0xffffffffu, mnew0, 1));
        mnew0 = fmaxf(mnew0, __shfl_xor_sync(0xffffffffu, mnew0, 2));
        mnew1 = fmaxf(mnew1, __shfl_xor_sync(0xffffffffu, mnew1, 1));
        mnew1 = fmaxf(mnew1, __shfl_xor_sync(0xffffffffu, mnew1, 2));

        float f0 = __expf(m_[0] - mnew0);
        float f1 = __expf(m_[1] - mnew1);
        float sum0 = 0.f, sum1 = 0.f;
        #pragma unroll
        for (int nt = 0; nt < 8; ++nt) {
            s[nt][0] = __expf(s[nt][0] - mnew0);
            s[nt][1] = __expf(s[nt][1] - mnew0);
            s[nt][2] = __expf(s[nt][2] - mnew1);
            s[nt][3] = __expf(s[nt][3] - mnew1);
            sum0 += s[nt][0] + s[nt][1];
            sum1 += s[nt][2] + s[nt][3];
        }
        sum0 += __shfl_xor_sync(0xffffffffu, sum0, 1);
        sum0 += __shfl_xor_sync(0xffffffffu, sum0, 2);
        sum1 += __shfl_xor_sync(0xffffffffu, sum1, 1);
        sum1 += __shfl_xor_sync(0xffffffffu, sum1, 2);
        l_[0] = l_[0] * f0 + sum0;
        l_[1] = l_[1] * f1 + sum1;
        m_[0] = mnew0;
        m_[1] = mnew1;

        #pragma unroll
        for (int nt = 0; nt < 8; ++nt) {
            o[nt][0] *= f0; o[nt][1] *= f0;
            o[nt][2] *= f1; o[nt][3] *= f1;
        }

        // ---- store P into this warp's A-frag region (frag kt = nt)
        #pragma unroll
        for (int nt = 0; nt < 8; ++nt) {
            unsigned* pb = Pw + (nt << 7);
            uint2 v0 = { tf32cvt(s[nt][0]), tf32cvt(s[nt][2]) };
            uint2 v1 = { tf32cvt(s[nt][1]), tf32cvt(s[nt][3]) };
            *reinterpret_cast<uint2*>(&pb[(plt << 2) + prr])       = v0;
            *reinterpret_cast<uint2*>(&pb[((plt + 1) << 2) + prr]) = v1;
        }
        __syncwarp();

        // ---- O += P @ V
        #pragma unroll
        for (int kt = 0; kt < 8; ++kt) {
            uint4 pa = *reinterpret_cast<const uint4*>(&Pw[(kt << 7) + (lane << 2)]);
            const int lx2 = (lane ^ (kt & 3)) << 1;
            #pragma unroll
            for (int nt = 0; nt < 8; ++nt) {
                uint2 bv = *reinterpret_cast<const uint2*>(&Vf[(((kt << 3) + nt) << 6) + lx2]);
                mma8(o[nt], pa.x, pa.y, pa.z, pa.w, bv.x, bv.y);
            }
        }
        __syncthreads();   // Kf/Vf consumed; safe to reload next jt
    }

    // ---- normalize + write z as [bs][h*64+e]
    float inv0 = 1.0f / l_[0];
    float inv1 = 1.0f / l_[1];
    int qr = qt * 64 + w * 16 + (lane >> 2);
    #pragma unroll
    for (int nt = 0; nt < 8; ++nt) {
        int e = nt * 8 + 2 * (lane & 3);
        size_t base0 = (size_t)(b * S_ + qr) * D_ + h * E_ + e;
        size_t base1 = (size_t)(b * S_ + qr + 8) * D_ + h * E_ + e;
        g_z[base0    ] = o[nt][0] * inv0;
        g_z[base0 + 1] = o[nt][1] * inv0;
        g_z[base1    ] = o[nt][2] * inv1;
        g_z[base1 + 1] = o[nt][3] * inv1;
    }
}

// ---------------------------------------------------------------------------
extern "C" void kernel_launch(void* const* d_in, const int* in_sizes, int n_in,
                              void* d_out, int out_size)
{
    const float* x  = (const float*)d_in[0];
    const float* WQ = (const float*)d_in[1];
    const float* WK = (const float*)d_in[2];
    const float* WV = (const float*)d_in[3];
    const float* WO = (const float*)d_in[4];
    const float* bQ = (const float*)d_in[5];
    const float* bK = (const float*)d_in[6];
    const float* bV = (const float*)d_in[7];
    const float* bO = (const float*)d_in[8];
    float* out = (float*)d_out;

    float *q, *k, *v;
    cudaGetSymbolAddress((void**)&q, g_q);
    cudaGetSymbolAddress((void**)&k, g_k);
    cudaGetSymbolAddress((void**)&v, g_v);

    // Weight transposes (K-major, tf32-rounded)
    transpose_qkv<<<dim3(24, 2, 36), 256>>>(WQ, WK, WV);
    transpose_wo<<<dim3(24, 24), 256>>>(WO);

    // QKV projection
    cudaFuncSetAttribute(qkv_frag, cudaFuncAttributeMaxDynamicSharedMemorySize, G_SMEM);
    qkv_frag<<<dim3(BS_ / 128, H_, 3), 256, G_SMEM>>>(x, bQ, bK, bV, q, k, v);

    // Flash attention
    cudaFuncSetAttribute(attn_frag, cudaFuncAttributeMaxDynamicSharedMemorySize, AT_SMEM);
    attn_frag<<<dim3(S_ / 64, H_, B_), 128, AT_SMEM>>>();

    // Output projection
    cudaFuncSetAttribute(out_frag, cudaFuncAttributeMaxDynamicSharedMemorySize, G_SMEM);
    out_frag<<<dim3(BS_ / 128, D_ / 64), 256, G_SMEM>>>(bO, out);
}

// round 13
// speedup vs baseline: 1.3398x; 1.3398x over previous
#include <cuda_runtime.h>
#include <math.h>

#define B_  4
#define S_  2048
#define D_  768
#define H_  12
#define E_  64
#define BS_ (B_ * S_)   // 8192

// Scratch (static device globals: allocation-free per harness rules)
__device__ float g_q[(size_t)B_ * H_ * S_ * E_];
__device__ float g_k[(size_t)B_ * H_ * S_ * E_];
__device__ float g_v[(size_t)B_ * H_ * S_ * E_];
__device__ float g_z[(size_t)BS_ * D_];

// ---------------------------------------------------------------------------
// tf32 helpers
// ---------------------------------------------------------------------------
__device__ __forceinline__ unsigned tf32cvt(float f) {
    unsigned u;
    asm("cvt.rna.tf32.f32 %0, %1;" : "=r"(u) : "f"(f));
    return u;
}

__device__ __forceinline__ void mma8(float c[4],
                                     unsigned a0, unsigned a1, unsigned a2, unsigned a3,
                                     unsigned b0, unsigned b1) {
    asm volatile(
        "mma.sync.aligned.m16n8k8.row.col.f32.tf32.tf32.f32 "
        "{%0,%1,%2,%3}, {%4,%5,%6,%7}, {%8,%9}, {%0,%1,%2,%3};\n"
        : "+f"(c[0]), "+f"(c[1]), "+f"(c[2]), "+f"(c[3])
        : "r"(a0), "r"(a1), "r"(a2), "r"(a3), "r"(b0), "r"(b1));
}

// ---------------------------------------------------------------------------
// Fused QKV projection. blockIdx.z in {0,1,2} selects Q/K/V.
// Block tile 128(M) x 64(N=E), K-tile 32. 256 threads = 8 warps (4x2).
// __launch_bounds__(256,4): cap 64 regs -> 4 CTAs/SM (regs were the limiter).
// ---------------------------------------------------------------------------
__global__ void __launch_bounds__(256, 4) qkv_gemm(
    const float* __restrict__ x,
    const float* __restrict__ WQ, const float* __restrict__ WK, const float* __restrict__ WV,
    const float* __restrict__ bQ, const float* __restrict__ bK, const float* __restrict__ bV,
    float* __restrict__ q, float* __restrict__ k, float* __restrict__ v)
{
    const float* W; const float* bias; float* out;
    if (blockIdx.z == 0)      { W = WQ; bias = bQ; out = q; }
    else if (blockIdx.z == 1) { W = WK; bias = bK; out = k; }
    else                      { W = WV; bias = bV; out = v; }

    __shared__ unsigned As[128][36];   // 128 rows x 32 K (pad 36)
    __shared__ unsigned Bs[32][72];    // 32 K x 64 N (pad 72)

    const int h    = blockIdx.y;
    const int row0 = blockIdx.x * 128;
    const int tid  = threadIdx.x;
    const int lane = tid & 31;
    const int wid  = tid >> 5;
    const int wm   = wid >> 1;      // 0..3
    const int wn   = wid & 1;       // 0..1

    const float* __restrict__ Wh = W + (size_t)h * D_ * E_;
    float acc[2][4][4] = {};

    for (int k0 = 0; k0 < D_; k0 += 32) {
        #pragma unroll
        for (int i = 0; i < 4; ++i) {
            int idx = tid + i * 256;
            int r   = idx >> 3;
            int c4  = (idx & 7) * 4;
            float4 v4 = *reinterpret_cast<const float4*>(&x[(size_t)(row0 + r) * D_ + k0 + c4]);
            uint4 u = { tf32cvt(v4.x), tf32cvt(v4.y), tf32cvt(v4.z), tf32cvt(v4.w) };
            *reinterpret_cast<uint4*>(&As[r][c4]) = u;
        }
        #pragma unroll
        for (int i = 0; i < 2; ++i) {
            int idx = tid + i * 256;
            int r   = idx >> 4;
            int c4  = (idx & 15) * 4;
            float4 v4 = *reinterpret_cast<const float4*>(&Wh[(size_t)(k0 + r) * E_ + c4]);
            uint4 u = { tf32cvt(v4.x), tf32cvt(v4.y), tf32cvt(v4.z), tf32cvt(v4.w) };
            *reinterpret_cast<uint4*>(&Bs[r][c4]) = u;
        }
        __syncthreads();

        #pragma unroll
        for (int kk = 0; kk < 4; ++kk) {
            const int ac = kk * 8 + (lane & 3);
            const int ar = wm * 32 + (lane >> 2);
            unsigned a[2][4];
            #pragma unroll
            for (int mt = 0; mt < 2; ++mt) {
                a[mt][0] = As[ar + mt * 16    ][ac];
                a[mt][1] = As[ar + mt * 16 + 8][ac];
                a[mt][2] = As[ar + mt * 16    ][ac + 4];
                a[mt][3] = As[ar + mt * 16 + 8][ac + 4];
            }
            const int bk = kk * 8 + (lane & 3);
            const int bn = wn * 32 + (lane >> 2);
            unsigned b[4][2];
            #pragma unroll
            for (int nt = 0; nt < 4; ++nt) {
                b[nt][0] = Bs[bk    ][bn + nt * 8];
                b[nt][1] = Bs[bk + 4][bn + nt * 8];
            }
            #pragma unroll
            for (int mt = 0; mt < 2; ++mt)
                #pragma unroll
                for (int nt = 0; nt < 4; ++nt)
                    mma8(acc[mt][nt], a[mt][0], a[mt][1], a[mt][2], a[mt][3],
                         b[nt][0], b[nt][1]);
        }
        __syncthreads();
    }

    #pragma unroll
    for (int mt = 0; mt < 2; ++mt) {
        #pragma unroll
        for (int rr = 0; rr < 2; ++rr) {
            int row = row0 + wm * 32 + mt * 16 + (lane >> 2) + rr * 8;
            int b_  = row / S_, s = row % S_;
            float* orow = out + ((size_t)(b_ * H_ + h) * S_ + s) * E_;
            #pragma unroll
            for (int nt = 0; nt < 4; ++nt) {
                int e = wn * 32 + nt * 8 + 2 * (lane & 3);
                orow[e    ] = acc[mt][nt][rr * 2    ] + bias[h * E_ + e];
                orow[e + 1] = acc[mt][nt][rr * 2 + 1] + bias[h * E_ + e + 1];
            }
        }
    }
}

// ---------------------------------------------------------------------------
// Flash attention, tf32 mma. Block = (b, h, 64-query tile), 128 threads.
// Warp w owns query rows w*16..w*16+15. Full register softmax (quad shfl).
// Dynamic smem: Qs[64][68], KPs[64][68] (K tile, then reused for P), Vs[64][72].
// __launch_bounds__(128,4): pin regs <= 128 so smem (53KB -> 4 CTAs) stays
// the occupancy limiter.
// ---------------------------------------------------------------------------
#define QS_STRIDE 68
#define VS_STRIDE 72

__global__ void __launch_bounds__(128, 4) attn_kernel()
{
    extern __shared__ unsigned sm_u[];
    unsigned* Qs  = sm_u;
    unsigned* KPs = Qs + 64 * QS_STRIDE;
    unsigned* Vs  = KPs + 64 * QS_STRIDE;

    const int qt  = blockIdx.x;
    const int h   = blockIdx.y;
    const int b   = blockIdx.z;
    const int tid = threadIdx.x;
    const int lane = tid & 31;
    const int w    = tid >> 5;

    const size_t bh = ((size_t)(b * H_ + h)) * S_ * E_;

    #pragma unroll
    for (int i = 0; i < 8; ++i) {
        int idx = tid + i * 128;
        int r   = idx >> 4;
        int c4  = (idx & 15) * 4;
        float4 v4 = *reinterpret_cast<const float4*>(&g_q[bh + (size_t)(qt * 64 + r) * E_ + c4]);
        uint4 u = { tf32cvt(v4.x), tf32cvt(v4.y), tf32cvt(v4.z), tf32cvt(v4.w) };
        *reinterpret_cast<uint4*>(&Qs[r * QS_STRIDE + c4]) = u;
    }
    __syncthreads();

    float o[8][4] = {};
    float m_[2] = { -1e30f, -1e30f };
    float l_[2] = { 0.f, 0.f };

    const int ar = w * 16 + (lane >> 2);
    const float scale = 0.125f;

    for (int jt = 0; jt <= qt; ++jt) {
        #pragma unroll
        for (int i = 0; i < 8; ++i) {
            int idx = tid + i * 128;
            int r   = idx >> 4;
            int c4  = (idx & 15) * 4;
            float4 kv4 = *reinterpret_cast<const float4*>(&g_k[bh + (size_t)(jt * 64 + r) * E_ + c4]);
            uint4 ku = { tf32cvt(kv4.x), tf32cvt(kv4.y), tf32cvt(kv4.z), tf32cvt(kv4.w) };
            *reinterpret_cast<uint4*>(&KPs[r * QS_STRIDE + c4]) = ku;
            float4 vv4 = *reinterpret_cast<const float4*>(&g_v[bh + (size_t)(jt * 64 + r) * E_ + c4]);
            uint4 vu = { tf32cvt(vv4.x), tf32cvt(vv4.y), tf32cvt(vv4.z), tf32cvt(vv4.w) };
            *reinterpret_cast<uint4*>(&Vs[r * VS_STRIDE + c4]) = vu;
        }
        __syncthreads();

        float s[8][4] = {};
        #pragma unroll
        for (int kk = 0; kk < 8; ++kk) {
            int ac = kk * 8 + (lane & 3);
            unsigned a0 = Qs[(ar    ) * QS_STRIDE + ac];
            unsigned a1 = Qs[(ar + 8) * QS_STRIDE + ac];
            unsigned a2 = Qs[(ar    ) * QS_STRIDE + ac + 4];
            unsigned a3 = Qs[(ar + 8) * QS_STRIDE + ac + 4];
            #pragma unroll
            for (int nt = 0; nt < 8; ++nt) {
                int brow = nt * 8 + (lane >> 2);
                unsigned b0 = KPs[brow * QS_STRIDE + ac];
                unsigned b1 = KPs[brow * QS_STRIDE + ac + 4];
                mma8(s[nt], a0, a1, a2, a3, b0, b1);
            }
        }

        const int qrow0 = qt * 64 + w * 16 + (lane >> 2);
        float mnew0 = m_[0], mnew1 = m_[1];
        #pragma unroll
        for (int nt = 0; nt < 8; ++nt) {
            int col = jt * 64 + nt * 8 + 2 * (lane & 3);
            float v0 = s[nt][0] * scale;
            float v1 = s[nt][1] * scale;
            float v2 = s[nt][2] * scale;
            float v3 = s[nt][3] * scale;
            if (jt == qt) {
                if (col     > qrow0)     v0 = -1e30f;
                if (col + 1 > qrow0)     v1 = -1e30f;
                if (col     > qrow0 + 8) v2 = -1e30f;
                if (col + 1 > qrow0 + 8) v3 = -1e30f;
            }
            s[nt][0] = v0; s[nt][1] = v1; s[nt][2] = v2; s[nt][3] = v3;
            mnew0 = fmaxf(mnew0, fmaxf(v0, v1));
            mnew1 = fmaxf(mnew1, fmaxf(v2, v3));
        }
        mnew0 = fmaxf(mnew0, __shfl_xor_sync(0xffffffffu, mnew0, 1));
        mnew0 = fmaxf(mnew0, __shfl_xor_sync(0xffffffffu, mnew0, 2));
        mnew1 = fmaxf(mnew1, __shfl_xor_sync(0xffffffffu, mnew1, 1));
        mnew1 = fmaxf(mnew1, __shfl_xor_sync(0xffffffffu, mnew1, 2));

        float f0 = __expf(m_[0] - mnew0);
        float f1 = __expf(m_[1] - mnew1);
        float sum0 = 0.f, sum1 = 0.f;
        #pragma unroll
        for (int nt = 0; nt < 8; ++nt) {
            s[nt][0] = __expf(s[nt][0] - mnew0);
            s[nt][1] = __expf(s[nt][1] - mnew0);
            s[nt][2] = __expf(s[nt][2] - mnew1);
            s[nt][3] = __expf(s[nt][3] - mnew1);
            sum0 += s[nt][0] + s[nt][1];
            sum1 += s[nt][2] + s[nt][3];
        }
        sum0 += __shfl_xor_sync(0xffffffffu, sum0, 1);
        sum0 += __shfl_xor_sync(0xffffffffu, sum0, 2);
        sum1 += __shfl_xor_sync(0xffffffffu, sum1, 1);
        sum1 += __shfl_xor_sync(0xffffffffu, sum1, 2);
        l_[0] = l_[0] * f0 + sum0;
        l_[1] = l_[1] * f1 + sum1;
        m_[0] = mnew0;
        m_[1] = mnew1;

        #pragma unroll
        for (int nt = 0; nt < 8; ++nt) {
            o[nt][0] *= f0; o[nt][1] *= f0;
            o[nt][2] *= f1; o[nt][3] *= f1;
        }

        // All warps must finish reading K before P overwrites the K tile
        __syncthreads();

        {
            int pr = w * 16 + (lane >> 2);
            #pragma unroll
            for (int nt = 0; nt < 8; ++nt) {
                int pc = nt * 8 + 2 * (lane & 3);
                KPs[(pr    ) * QS_STRIDE + pc    ] = tf32cvt(s[nt][0]);
                KPs[(pr    ) * QS_STRIDE + pc + 1] = tf32cvt(s[nt][1]);
                KPs[(pr + 8) * QS_STRIDE + pc    ] = tf32cvt(s[nt][2]);
                KPs[(pr + 8) * QS_STRIDE + pc + 1] = tf32cvt(s[nt][3]);
            }
        }
        __syncwarp();   // P@V reads only this warp's rows of KPs

        #pragma unroll
        for (int kk = 0; kk < 8; ++kk) {
            int ac = kk * 8 + (lane & 3);
            unsigned a0 = KPs[(ar    ) * QS_STRIDE + ac];
            unsigned a1 = KPs[(ar + 8) * QS_STRIDE + ac];
            unsigned a2 = KPs[(ar    ) * QS_STRIDE + ac + 4];
            unsigned a3 = KPs[(ar + 8) * QS_STRIDE + ac + 4];
            #pragma unroll
            for (int nt = 0; nt < 8; ++nt) {
                int bn = nt * 8 + (lane >> 2);
                unsigned b0 = Vs[(kk * 8 + (lane & 3)    ) * VS_STRIDE + bn];
                unsigned b1 = Vs[(kk * 8 + (lane & 3) + 4) * VS_STRIDE + bn];
                mma8(o[nt], a0, a1, a2, a3, b0, b1);
            }
        }
        __syncthreads();   // guard K/V reload and P overwrite next iter
    }

    float inv0 = 1.0f / l_[0];
    float inv1 = 1.0f / l_[1];
    int qr = qt * 64 + w * 16 + (lane >> 2);
    #pragma unroll
    for (int nt = 0; nt < 8; ++nt) {
        int e = nt * 8 + 2 * (lane & 3);
        size_t base0 = (size_t)(b * S_ + qr) * D_ + h * E_ + e;
        size_t base1 = (size_t)(b * S_ + qr + 8) * D_ + h * E_ + e;
        g_z[base0    ] = o[nt][0] * inv0;
        g_z[base0 + 1] = o[nt][1] * inv0;
        g_z[base1    ] = o[nt][2] * inv1;
        g_z[base1 + 1] = o[nt][3] * inv1;
    }
}

// ---------------------------------------------------------------------------
// Output projection: [8192 x 768] = z[8192 x 768] @ Wo[768 x 768] + bO
// ---------------------------------------------------------------------------
__global__ void __launch_bounds__(256, 4) out_proj(
    const float* __restrict__ Wo, const float* __restrict__ bO,
    float* __restrict__ out)
{
    __shared__ unsigned As[128][36];
    __shared__ unsigned Bs[32][72];

    const int n0   = blockIdx.y * 64;
    const int row0 = blockIdx.x * 128;
    const int tid  = threadIdx.x;
    const int lane = tid & 31;
    const int wid  = tid >> 5;
    const int wm   = wid >> 1;
    const int wn   = wid & 1;

    float acc[2][4][4] = {};

    for (int k0 = 0; k0 < D_; k0 += 32) {
        #pragma unroll
        for (int i = 0; i < 4; ++i) {
            int idx = tid + i * 256;
            int r   = idx >> 3;
            int c4  = (idx & 7) * 4;
            float4 v4 = *reinterpret_cast<const float4*>(&g_z[(size_t)(row0 + r) * D_ + k0 + c4]);
            uint4 u = { tf32cvt(v4.x), tf32cvt(v4.y), tf32cvt(v4.z), tf32cvt(v4.w) };
            *reinterpret_cast<uint4*>(&As[r][c4]) = u;
        }
        #pragma unroll
        for (int i = 0; i < 2; ++i) {
            int idx = tid + i * 256;
            int r   = idx >> 4;
            int c4  = (idx & 15) * 4;
            float4 v4 = *reinterpret_cast<const float4*>(&Wo[(size_t)(k0 + r) * D_ + n0 + c4]);
            uint4 u = { tf32cvt(v4.x), tf32cvt(v4.y), tf32cvt(v4.z), tf32cvt(v4.w) };
            *reinterpret_cast<uint4*>(&Bs[r][c4]) = u;
        }
        __syncthreads();

        #pragma unroll
        for (int kk = 0; kk < 4; ++kk) {
            const int ac = kk * 8 + (lane & 3);
            const int ar = wm * 32 + (lane >> 2);
            unsigned a[2][4];
            #pragma unroll
            for (int mt = 0; mt < 2; ++mt) {
                a[mt][0] = As[ar + mt * 16    ][ac];
                a[mt][1] = As[ar + mt * 16 + 8][ac];
                a[mt][2] = As[ar + mt * 16    ][ac + 4];
                a[mt][3] = As[ar + mt * 16 + 8][ac + 4];
            }
            const int bk = kk * 8 + (lane & 3);
            const int bn = wn * 32 + (lane >> 2);
            unsigned b[4][2];
            #pragma unroll
            for (int nt = 0; nt < 4; ++nt) {
                b[nt][0] = Bs[bk    ][bn + nt * 8];
                b[nt][1] = Bs[bk + 4][bn + nt * 8];
            }
            #pragma unroll
            for (int mt = 0; mt < 2; ++mt)
                #pragma unroll
                for (int nt = 0; nt < 4; ++nt)
                    mma8(acc[mt][nt], a[mt][0], a[mt][1], a[mt][2], a[mt][3],
                         b[nt][0], b[nt][1]);
        }
        __syncthreads();
    }

    #pragma unroll
    for (int mt = 0; mt < 2; ++mt) {
        #pragma unroll
        for (int rr = 0; rr < 2; ++rr) {
            int row = row0 + wm * 32 + mt * 16 + (lane >> 2) + rr * 8;
            #pragma unroll
            for (int nt = 0; nt < 4; ++nt) {
                int d = n0 + wn * 32 + nt * 8 + 2 * (lane & 3);
                out[(size_t)row * D_ + d    ] = acc[mt][nt][rr * 2    ] + bO[d];
                out[(size_t)row * D_ + d + 1] = acc[mt][nt][rr * 2 + 1] + bO[d + 1];
            }
        }
    }
}

// ---------------------------------------------------------------------------
extern "C" void kernel_launch(void* const* d_in, const int* in_sizes, int n_in,
                              void* d_out, int out_size)
{
    const float* x  = (const float*)d_in[0];
    const float* WQ = (const float*)d_in[1];
    const float* WK = (const float*)d_in[2];
    const float* WV = (const float*)d_in[3];
    const float* WO = (const float*)d_in[4];
    const float* bQ = (const float*)d_in[5];
    const float* bK = (const float*)d_in[6];
    const float* bV = (const float*)d_in[7];
    const float* bO = (const float*)d_in[8];
    float* out = (float*)d_out;

    float *q, *k, *v;
    cudaGetSymbolAddress((void**)&q, g_q);
    cudaGetSymbolAddress((void**)&k, g_k);
    cudaGetSymbolAddress((void**)&v, g_v);

    // Fused QKV projections
    dim3 gq(BS_ / 128, H_, 3);
    qkv_gemm<<<gq, 256>>>(x, WQ, WK, WV, bQ, bK, bV, q, k, v);

    // Flash attention (tf32 mma.sync), dynamic smem
    const int attn_smem = 64 * (QS_STRIDE + QS_STRIDE + VS_STRIDE) * (int)sizeof(unsigned);
    cudaFuncSetAttribute(attn_kernel, cudaFuncAttributeMaxDynamicSharedMemorySize, attn_smem);
    dim3 ga(S_ / 64, H_, B_);
    attn_kernel<<<ga, 128, attn_smem>>>();

    // Output projection
    dim3 gp(BS_ / 128, D_ / 64);
    out_proj<<<gp, 256>>>(WO, bO, out);
}

// round 14
// speedup vs baseline: 1.5355x; 1.1461x over previous
#include <cuda_runtime.h>
#include <cstdint>
#include <math.h>

#define B_  4
#define S_  2048
#define D_  768
#define H_  12
#define E_  64
#define BS_ (B_ * S_)   // 8192

// Scratch (static device globals: allocation-free per harness rules)
__device__ float g_q[(size_t)B_ * H_ * S_ * E_];
__device__ float g_k[(size_t)B_ * H_ * S_ * E_];
__device__ float g_v[(size_t)B_ * H_ * S_ * E_];
__device__ float g_z[(size_t)BS_ * D_];
__device__ float g_xt [(size_t)BS_ * D_];        // x, tf32-rounded
__device__ float g_wqr[(size_t)H_ * D_ * E_];    // W_Q, tf32-rounded
__device__ float g_wkr[(size_t)H_ * D_ * E_];
__device__ float g_wvr[(size_t)H_ * D_ * E_];
__device__ float g_wor[(size_t)D_ * D_];         // W_O, tf32-rounded

// ---------------------------------------------------------------------------
__device__ __forceinline__ unsigned tf32cvt(float f) {
    unsigned u;
    asm("cvt.rna.tf32.f32 %0, %1;" : "=r"(u) : "f"(f));
    return u;
}

__device__ __forceinline__ void mma8(float c[4],
                                     unsigned a0, unsigned a1, unsigned a2, unsigned a3,
                                     unsigned b0, unsigned b1) {
    asm volatile(
        "mma.sync.aligned.m16n8k8.row.col.f32.tf32.tf32.f32 "
        "{%0,%1,%2,%3}, {%4,%5,%6,%7}, {%8,%9}, {%0,%1,%2,%3};\n"
        : "+f"(c[0]), "+f"(c[1]), "+f"(c[2]), "+f"(c[3])
        : "r"(a0), "r"(a1), "r"(a2), "r"(a3), "r"(b0), "r"(b1));
}

__device__ __forceinline__ uint32_t smem_u32(const void* p) {
    uint32_t a;
    asm("{ .reg .u64 t; cvta.to.shared.u64 t, %1; cvt.u32.u64 %0, t; }" : "=r"(a) : "l"(p));
    return a;
}

__device__ __forceinline__ void cp16(uint32_t dst, const void* src) {
    asm volatile("cp.async.cg.shared.global [%0], [%1], 16;" :: "r"(dst), "l"(src));
}
#define CP_COMMIT() asm volatile("cp.async.commit_group;" ::: "memory")
#define CP_WAIT0()  asm volatile("cp.async.wait_group 0;" ::: "memory")
#define CP_WAIT1()  asm volatile("cp.async.wait_group 1;" ::: "memory")

// ---------------------------------------------------------------------------
// tf32 pre-rounding (grid-stride-free, one float4 per thread)
// ---------------------------------------------------------------------------
__global__ void __launch_bounds__(256) round_tf32(
    const float* __restrict__ s, float* __restrict__ d, int n4)
{
    int i = blockIdx.x * 256 + threadIdx.x;
    if (i < n4) {
        float4 f = reinterpret_cast<const float4*>(s)[i];
        uint4 u = { tf32cvt(f.x), tf32cvt(f.y), tf32cvt(f.z), tf32cvt(f.w) };
        reinterpret_cast<uint4*>(d)[i] = u;
    }
}

// ---------------------------------------------------------------------------
// cp.async double-buffered GEMM core. Block tile 128(M) x 64(N), K-tile 32,
// 256 threads = 8 warps (4m x 2n), warp tile 32x32.
// Dynamic smem (words): A[2] @ 0/4608 (128x36), B[2] @ 9216/+2304 (32x72).
// ---------------------------------------------------------------------------
#define A_W(b)   ((b) * 4608)
#define B_W(b)   (9216 + (b) * 2304)
#define G_SMEM_B 55296

__device__ __forceinline__ void g_tile_ca(
    unsigned* sm, int buf, const float* __restrict__ Asrc,
    const float* __restrict__ Bsrc, int bstride, int tid, int k0)
{
    #pragma unroll
    for (int i = 0; i < 4; ++i) {                 // A: 1024 16B chunks
        int idx = tid + i * 256;
        int r = idx >> 3, c4 = (idx & 7) * 4;
        cp16(smem_u32(&sm[A_W(buf) + r * 36 + c4]),
             Asrc + (size_t)r * D_ + k0 + c4);
    }
    #pragma unroll
    for (int i = 0; i < 2; ++i) {                 // B: 512 16B chunks
        int idx = tid + i * 256;
        int r = idx >> 4, c4 = (idx & 15) * 4;
        cp16(smem_u32(&sm[B_W(buf) + r * 72 + c4]),
             Bsrc + (size_t)(k0 + r) * bstride + c4);
    }
}

__device__ __forceinline__ void g_compute(
    const unsigned* sm, int buf, int wm, int wn, int lane, float acc[2][4][4])
{
    const unsigned* As = sm + A_W(buf);
    const unsigned* Bs = sm + B_W(buf);
    #pragma unroll
    for (int kk = 0; kk < 4; ++kk) {
        const int ac = kk * 8 + (lane & 3);
        const int ar = wm * 32 + (lane >> 2);
        unsigned a[2][4];
        #pragma unroll
        for (int mt = 0; mt < 2; ++mt) {
            a[mt][0] = As[(ar + mt * 16    ) * 36 + ac];
            a[mt][1] = As[(ar + mt * 16 + 8) * 36 + ac];
            a[mt][2] = As[(ar + mt * 16    ) * 36 + ac + 4];
            a[mt][3] = As[(ar + mt * 16 + 8) * 36 + ac + 4];
        }
        const int bk = kk * 8 + (lane & 3);
        const int bn = wn * 32 + (lane >> 2);
        unsigned b[4][2];
        #pragma unroll
        for (int nt = 0; nt < 4; ++nt) {
            b[nt][0] = Bs[bk * 72 + bn + nt * 8];
            b[nt][1] = Bs[(bk + 4) * 72 + bn + nt * 8];
        }
        #pragma unroll
        for (int mt = 0; mt < 2; ++mt)
            #pragma unroll
            for (int nt = 0; nt < 4; ++nt)
                mma8(acc[mt][nt], a[mt][0], a[mt][1], a[mt][2], a[mt][3],
                     b[nt][0], b[nt][1]);
    }
}

// QKV projection: grid (64, H, 3). Output written tf32-rounded (consumed by attn).
__global__ void __launch_bounds__(256, 4) qkv_gemm(
    const float* __restrict__ bQ, const float* __restrict__ bK, const float* __restrict__ bV,
    float* __restrict__ q, float* __restrict__ k, float* __restrict__ v)
{
    extern __shared__ unsigned sm[];
    const int row0 = blockIdx.x * 128;
    const int h    = blockIdx.y;
    const int m    = blockIdx.z;
    const int tid  = threadIdx.x;
    const int lane = tid & 31;
    const int wid  = tid >> 5;
    const int wm   = wid >> 1, wn = wid & 1;

    const float* Asrc = g_xt + (size_t)row0 * D_;
    const float* W    = (m == 0 ? g_wqr : m == 1 ? g_wkr : g_wvr) + (size_t)h * D_ * E_;
    float* out        = m == 0 ? q : m == 1 ? k : v;
    const float* bias = m == 0 ? bQ : m == 1 ? bK : bV;

    float acc[2][4][4] = {};

    g_tile_ca(sm, 0, Asrc, W, E_, tid, 0);
    CP_COMMIT();
    for (int t = 0; t < 24; ++t) {
        if (t + 1 < 24) {
            g_tile_ca(sm, (t + 1) & 1, Asrc, W, E_, tid, (t + 1) * 32);
            CP_COMMIT();
            CP_WAIT1();
        } else {
            CP_WAIT0();
        }
        __syncthreads();
        g_compute(sm, t & 1, wm, wn, lane, acc);
        __syncthreads();
    }

    #pragma unroll
    for (int mt = 0; mt < 2; ++mt) {
        #pragma unroll
        for (int rr = 0; rr < 2; ++rr) {
            int row = row0 + wm * 32 + mt * 16 + (lane >> 2) + rr * 8;
            int b_  = row / S_, s = row % S_;
            float* orow = out + ((size_t)(b_ * H_ + h) * S_ + s) * E_;
            #pragma unroll
            for (int nt = 0; nt < 4; ++nt) {
                int e = wn * 32 + nt * 8 + 2 * (lane & 3);
                orow[e    ] = __uint_as_float(tf32cvt(acc[mt][nt][rr * 2    ] + bias[h * E_ + e]));
                orow[e + 1] = __uint_as_float(tf32cvt(acc[mt][nt][rr * 2 + 1] + bias[h * E_ + e + 1]));
            }
        }
    }
}

// Output projection: grid (64, 12). Final output stays fp32 (no rounding).
__global__ void __launch_bounds__(256, 4) out_proj(
    const float* __restrict__ bO, float* __restrict__ out)
{
    extern __shared__ unsigned sm[];
    const int row0 = blockIdx.x * 128;
    const int n0   = blockIdx.y * 64;
    const int tid  = threadIdx.x;
    const int lane = tid & 31;
    const int wid  = tid >> 5;
    const int wm   = wid >> 1, wn = wid & 1;

    const float* Asrc = g_z + (size_t)row0 * D_;
    const float* Bsrc = g_wor + n0;          // row k: g_wor[k*768 + n0 + c]

    float acc[2][4][4] = {};

    g_tile_ca(sm, 0, Asrc, Bsrc, D_, tid, 0);
    CP_COMMIT();
    for (int t = 0; t < 24; ++t) {
        if (t + 1 < 24) {
            g_tile_ca(sm, (t + 1) & 1, Asrc, Bsrc, D_, tid, (t + 1) * 32);
            CP_COMMIT();
            CP_WAIT1();
        } else {
            CP_WAIT0();
        }
        __syncthreads();
        g_compute(sm, t & 1, wm, wn, lane, acc);
        __syncthreads();
    }

    #pragma unroll
    for (int mt = 0; mt < 2; ++mt) {
        #pragma unroll
        for (int rr = 0; rr < 2; ++rr) {
            int row = row0 + wm * 32 + mt * 16 + (lane >> 2) + rr * 8;
            #pragma unroll
            for (int nt = 0; nt < 4; ++nt) {
                int d = n0 + wn * 32 + nt * 8 + 2 * (lane & 3);
                out[(size_t)row * D_ + d    ] = acc[mt][nt][rr * 2    ] + bO[d];
                out[(size_t)row * D_ + d + 1] = acc[mt][nt][rr * 2 + 1] + bO[d + 1];
            }
        }
    }
}

// ---------------------------------------------------------------------------
// Flash attention, tf32 mma.sync. Inputs q/k/v are already tf32-rounded, so
// tiles are fetched with raw cp.async (no cvt, no register staging).
// Dynamic smem: Qs[64][68], KPs[64][68] (K tile, then reused for P), Vs[64][72].
// ---------------------------------------------------------------------------
#define QS_STRIDE 68
#define VS_STRIDE 72

__global__ void __launch_bounds__(128, 4) attn_kernel()
{
    extern __shared__ unsigned sm_u[];
    unsigned* Qs  = sm_u;
    unsigned* KPs = Qs + 64 * QS_STRIDE;
    unsigned* Vs  = KPs + 64 * QS_STRIDE;

    const int qt  = blockIdx.x;
    const int h   = blockIdx.y;
    const int b   = blockIdx.z;
    const int tid = threadIdx.x;
    const int lane = tid & 31;
    const int w    = tid >> 5;

    const size_t bh = ((size_t)(b * H_ + h)) * S_ * E_;

    // Q tile via cp.async
    #pragma unroll
    for (int i = 0; i < 8; ++i) {
        int idx = tid + i * 128;
        int r = idx >> 4, c4 = (idx & 15) * 4;
        cp16(smem_u32(&Qs[r * QS_STRIDE + c4]),
             &g_q[bh + (size_t)(qt * 64 + r) * E_ + c4]);
    }
    CP_COMMIT(); CP_WAIT0();
    __syncthreads();

    float o[8][4] = {};
    float m_[2] = { -1e30f, -1e30f };
    float l_[2] = { 0.f, 0.f };

    const int ar = w * 16 + (lane >> 2);
    const float scale = 0.125f;

    for (int jt = 0; jt <= qt; ++jt) {
        // K, V tiles via cp.async
        #pragma unroll
        for (int i = 0; i < 8; ++i) {
            int idx = tid + i * 128;
            int r = idx >> 4, c4 = (idx & 15) * 4;
            cp16(smem_u32(&KPs[r * QS_STRIDE + c4]),
                 &g_k[bh + (size_t)(jt * 64 + r) * E_ + c4]);
            cp16(smem_u32(&Vs[r * VS_STRIDE + c4]),
                 &g_v[bh + (size_t)(jt * 64 + r) * E_ + c4]);
        }
        CP_COMMIT(); CP_WAIT0();
        __syncthreads();

        float s[8][4] = {};
        #pragma unroll
        for (int kk = 0; kk < 8; ++kk) {
            int ac = kk * 8 + (lane & 3);
            unsigned a0 = Qs[(ar    ) * QS_STRIDE + ac];
            unsigned a1 = Qs[(ar + 8) * QS_STRIDE + ac];
            unsigned a2 = Qs[(ar    ) * QS_STRIDE + ac + 4];
            unsigned a3 = Qs[(ar + 8) * QS_STRIDE + ac + 4];
            #pragma unroll
            for (int nt = 0; nt < 8; ++nt) {
                int brow = nt * 8 + (lane >> 2);
                unsigned b0 = KPs[brow * QS_STRIDE + ac];
                unsigned b1 = KPs[brow * QS_STRIDE + ac + 4];
                mma8(s[nt], a0, a1, a2, a3, b0, b1);
            }
        }

        const int qrow0 = qt * 64 + w * 16 + (lane >> 2);
        float mnew0 = m_[0], mnew1 = m_[1];
        #pragma unroll
        for (int nt = 0; nt < 8; ++nt) {
            int col = jt * 64 + nt * 8 + 2 * (lane & 3);
            float v0 = s[nt][0] * scale;
            float v1 = s[nt][1] * scale;
            float v2 = s[nt][2] * scale;
            float v3 = s[nt][3] * scale;
            if (jt == qt) {
                if (col     > qrow0)     v0 = -1e30f;
                if (col + 1 > qrow0)     v1 = -1e30f;
                if (col     > qrow0 + 8) v2 = -1e30f;
                if (col + 1 > qrow0 + 8) v3 = -1e30f;
            }
            s[nt][0] = v0; s[nt][1] = v1; s[nt][2] = v2; s[nt][3] = v3;
            mnew0 = fmaxf(mnew0, fmaxf(v0, v1));
            mnew1 = fmaxf(mnew1, fmaxf(v2, v3));
        }
        mnew0 = fmaxf(mnew0, __shfl_xor_sync(0xffffffffu, mnew0, 1));
        mnew0 = fmaxf(mnew0, __shfl_xor_sync(0xffffffffu, mnew0, 2));
        mnew1 = fmaxf(mnew1, __shfl_xor_sync(0xffffffffu, mnew1, 1));
        mnew1 = fmaxf(mnew1, __shfl_xor_sync(0xffffffffu, mnew1, 2));

        float f0 = __expf(m_[0] - mnew0);
        float f1 = __expf(m_[1] - mnew1);
        float sum0 = 0.f, sum1 = 0.f;
        #pragma unroll
        for (int nt = 0; nt < 8; ++nt) {
            s[nt][0] = __expf(s[nt][0] - mnew0);
            s[nt][1] = __expf(s[nt][1] - mnew0);
            s[nt][2] = __expf(s[nt][2] - mnew1);
            s[nt][3] = __expf(s[nt][3] - mnew1);
            sum0 += s[nt][0] + s[nt][1];
            sum1 += s[nt][2] + s[nt][3];
        }
        sum0 += __shfl_xor_sync(0xffffffffu, sum0, 1);
        sum0 += __shfl_xor_sync(0xffffffffu, sum0, 2);
        sum1 += __shfl_xor_sync(0xffffffffu, sum1, 1);
        sum1 += __shfl_xor_sync(0xffffffffu, sum1, 2);
        l_[0] = l_[0] * f0 + sum0;
        l_[1] = l_[1] * f1 + sum1;
        m_[0] = mnew0;
        m_[1] = mnew1;

        #pragma unroll
        for (int nt = 0; nt < 8; ++nt) {
            o[nt][0] *= f0; o[nt][1] *= f0;
            o[nt][2] *= f1; o[nt][3] *= f1;
        }

        // All warps must finish reading K before P overwrites the K tile
        __syncthreads();

        {
            int pr = w * 16 + (lane >> 2);
            #pragma unroll
            for (int nt = 0; nt < 8; ++nt) {
                int pc = nt * 8 + 2 * (lane & 3);
                KPs[(pr    ) * QS_STRIDE + pc    ] = tf32cvt(s[nt][0]);
                KPs[(pr    ) * QS_STRIDE + pc + 1] = tf32cvt(s[nt][1]);
                KPs[(pr + 8) * QS_STRIDE + pc    ] = tf32cvt(s[nt][2]);
                KPs[(pr + 8) * QS_STRIDE + pc + 1] = tf32cvt(s[nt][3]);
            }
        }
        __syncwarp();   // P@V reads only this warp's rows of KPs

        #pragma unroll
        for (int kk = 0; kk < 8; ++kk) {
            int ac = kk * 8 + (lane & 3);
            unsigned a0 = KPs[(ar    ) * QS_STRIDE + ac];
            unsigned a1 = KPs[(ar + 8) * QS_STRIDE + ac];
            unsigned a2 = KPs[(ar    ) * QS_STRIDE + ac + 4];
            unsigned a3 = KPs[(ar + 8) * QS_STRIDE + ac + 4];
            #pragma unroll
            for (int nt = 0; nt < 8; ++nt) {
                int bn = nt * 8 + (lane >> 2);
                unsigned b0 = Vs[(kk * 8 + (lane & 3)    ) * VS_STRIDE + bn];
                unsigned b1 = Vs[(kk * 8 + (lane & 3) + 4) * VS_STRIDE + bn];
                mma8(o[nt], a0, a1, a2, a3, b0, b1);
            }
        }
        __syncthreads();   // guard K/V reload and P overwrite next iter
    }

    // normalize + write z (tf32-rounded; out_proj consumes raw)
    float inv0 = 1.0f / l_[0];
    float inv1 = 1.0f / l_[1];
    int qr = qt * 64 + w * 16 + (lane >> 2);
    #pragma unroll
    for (int nt = 0; nt < 8; ++nt) {
        int e = nt * 8 + 2 * (lane & 3);
        size_t base0 = (size_t)(b * S_ + qr) * D_ + h * E_ + e;
        size_t base1 = (size_t)(b * S_ + qr + 8) * D_ + h * E_ + e;
        g_z[base0    ] = __uint_as_float(tf32cvt(o[nt][0] * inv0));
        g_z[base0 + 1] = __uint_as_float(tf32cvt(o[nt][1] * inv0));
        g_z[base1    ] = __uint_as_float(tf32cvt(o[nt][2] * inv1));
        g_z[base1 + 1] = __uint_as_float(tf32cvt(o[nt][3] * inv1));
    }
}

// ---------------------------------------------------------------------------
extern "C" void kernel_launch(void* const* d_in, const int* in_sizes, int n_in,
                              void* d_out, int out_size)
{
    const float* x  = (const float*)d_in[0];
    const float* WQ = (const float*)d_in[1];
    const float* WK = (const float*)d_in[2];
    const float* WV = (const float*)d_in[3];
    const float* WO = (const float*)d_in[4];
    const float* bQ = (const float*)d_in[5];
    const float* bK = (const float*)d_in[6];
    const float* bV = (const float*)d_in[7];
    const float* bO = (const float*)d_in[8];
    float* out = (float*)d_out;

    float *q, *k, *v, *xt, *wqr, *wkr, *wvr, *wor;
    cudaGetSymbolAddress((void**)&q,   g_q);
    cudaGetSymbolAddress((void**)&k,   g_k);
    cudaGetSymbolAddress((void**)&v,   g_v);
    cudaGetSymbolAddress((void**)&xt,  g_xt);
    cudaGetSymbolAddress((void**)&wqr, g_wqr);
    cudaGetSymbolAddress((void**)&wkr, g_wkr);
    cudaGetSymbolAddress((void**)&wvr, g_wvr);
    cudaGetSymbolAddress((void**)&wor, g_wor);

    // Pre-round everything to tf32 (bit-identical dataflow to cvt-on-load)
    const int n4x = BS_ * D_ / 4;           // 1572864
    const int n4w = H_ * D_ * E_ / 4;       // 147456
    const int n4o = D_ * D_ / 4;            // 147456
    round_tf32<<<(n4x + 255) / 256, 256>>>(x,  xt,  n4x);
    round_tf32<<<(n4w + 255) / 256, 256>>>(WQ, wqr, n4w);
    round_tf32<<<(n4w + 255) / 256, 256>>>(WK, wkr, n4w);
    round_tf32<<<(n4w + 255) / 256, 256>>>(WV, wvr, n4w);
    round_tf32<<<(n4o + 255) / 256, 256>>>(WO, wor, n4o);

    // QKV projections (cp.async double-buffered)
    cudaFuncSetAttribute(qkv_gemm, cudaFuncAttributeMaxDynamicSharedMemorySize, G_SMEM_B);
    qkv_gemm<<<dim3(BS_ / 128, H_, 3), 256, G_SMEM_B>>>(bQ, bK, bV, q, k, v);

    // Flash attention
    const int attn_smem = 64 * (QS_STRIDE + QS_STRIDE + VS_STRIDE) * (int)sizeof(unsigned);
    cudaFuncSetAttribute(attn_kernel, cudaFuncAttributeMaxDynamicSharedMemorySize, attn_smem);
    attn_kernel<<<dim3(S_ / 64, H_, B_), 128, attn_smem>>>();

    // Output projection (cp.async double-buffered)
    cudaFuncSetAttribute(out_proj, cudaFuncAttributeMaxDynamicSharedMemorySize, G_SMEM_B);
    out_proj<<<dim3(BS_ / 128, D_ / 64), 256, G_SMEM_B>>>(bO, out);
}

// round 15
// speedup vs baseline: 1.5996x; 1.0417x over previous
#include <cuda_runtime.h>
#include <cstdint>
#include <math.h>

#define B_  4
#define S_  2048
#define D_  768
#define H_  12
#define E_  64
#define BS_ (B_ * S_)   // 8192

// Scratch (static device globals: allocation-free per harness rules)
__device__ float g_q[(size_t)B_ * H_ * S_ * E_];   // [bh][s][e-interleaved]
__device__ float g_k[(size_t)B_ * H_ * S_ * E_];   // [bh][s][e-interleaved]
__device__ float g_vt[(size_t)B_ * H_ * E_ * S_];  // [bh][e][s-interleaved]
__device__ float g_z[(size_t)BS_ * D_];
__device__ float g_xt [(size_t)BS_ * D_];          // x, tf32-rounded
__device__ float g_wqr[(size_t)H_ * D_ * E_];      // W_Q, tf32-rounded
__device__ float g_wkr[(size_t)H_ * D_ * E_];
__device__ float g_wvr[(size_t)H_ * D_ * E_];
__device__ float g_wor[(size_t)D_ * D_];           // W_O, tf32-rounded

// ---------------------------------------------------------------------------
__device__ __forceinline__ unsigned tf32cvt(float f) {
    unsigned u;
    asm("cvt.rna.tf32.f32 %0, %1;" : "=r"(u) : "f"(f));
    return u;
}

__device__ __forceinline__ void mma8(float c[4],
                                     unsigned a0, unsigned a1, unsigned a2, unsigned a3,
                                     unsigned b0, unsigned b1) {
    asm volatile(
        "mma.sync.aligned.m16n8k8.row.col.f32.tf32.tf32.f32 "
        "{%0,%1,%2,%3}, {%4,%5,%6,%7}, {%8,%9}, {%0,%1,%2,%3};\n"
        : "+f"(c[0]), "+f"(c[1]), "+f"(c[2]), "+f"(c[3])
        : "r"(a0), "r"(a1), "r"(a2), "r"(a3), "r"(b0), "r"(b1));
}

__device__ __forceinline__ uint32_t smem_u32(const void* p) {
    uint32_t a;
    asm("{ .reg .u64 t; cvta.to.shared.u64 t, %1; cvt.u32.u64 %0, t; }" : "=r"(a) : "l"(p));
    return a;
}

__device__ __forceinline__ void cp16(uint32_t dst, const void* src) {
    asm volatile("cp.async.cg.shared.global [%0], [%1], 16;" :: "r"(dst), "l"(src));
}
#define CP_COMMIT() asm volatile("cp.async.commit_group;" ::: "memory")
#define CP_WAIT0()  asm volatile("cp.async.wait_group 0;" ::: "memory")
#define CP_WAIT1()  asm volatile("cp.async.wait_group 1;" ::: "memory")

// pair-interleave within 8-groups: w -> (w<4 ? 2w : 2w-7)
__device__ __forceinline__ int perm8(int w) { return (w < 4) ? 2 * w : 2 * w - 7; }

// ---------------------------------------------------------------------------
__global__ void __launch_bounds__(256) round_tf32(
    const float* __restrict__ s, float* __restrict__ d, int n4)
{
    int i = blockIdx.x * 256 + threadIdx.x;
    if (i < n4) {
        float4 f = reinterpret_cast<const float4*>(s)[i];
        uint4 u = { tf32cvt(f.x), tf32cvt(f.y), tf32cvt(f.z), tf32cvt(f.w) };
        reinterpret_cast<uint4*>(d)[i] = u;
    }
}

// ---------------------------------------------------------------------------
// cp.async double-buffered GEMM core (unchanged from round 14).
// ---------------------------------------------------------------------------
#define A_W(b)   ((b) * 4608)
#define B_W(b)   (9216 + (b) * 2304)
#define G_SMEM_B 55296

__device__ __forceinline__ void g_tile_ca(
    unsigned* sm, int buf, const float* __restrict__ Asrc,
    const float* __restrict__ Bsrc, int bstride, int tid, int k0)
{
    #pragma unroll
    for (int i = 0; i < 4; ++i) {
        int idx = tid + i * 256;
        int r = idx >> 3, c4 = (idx & 7) * 4;
        cp16(smem_u32(&sm[A_W(buf) + r * 36 + c4]),
             Asrc + (size_t)r * D_ + k0 + c4);
    }
    #pragma unroll
    for (int i = 0; i < 2; ++i) {
        int idx = tid + i * 256;
        int r = idx >> 4, c4 = (idx & 15) * 4;
        cp16(smem_u32(&sm[B_W(buf) + r * 72 + c4]),
             Bsrc + (size_t)(k0 + r) * bstride + c4);
    }
}

__device__ __forceinline__ void g_compute(
    const unsigned* sm, int buf, int wm, int wn, int lane, float acc[2][4][4])
{
    const unsigned* As = sm + A_W(buf);
    const unsigned* Bs = sm + B_W(buf);
    #pragma unroll
    for (int kk = 0; kk < 4; ++kk) {
        const int ac = kk * 8 + (lane & 3);
        const int ar = wm * 32 + (lane >> 2);
        unsigned a[2][4];
        #pragma unroll
        for (int mt = 0; mt < 2; ++mt) {
            a[mt][0] = As[(ar + mt * 16    ) * 36 + ac];
            a[mt][1] = As[(ar + mt * 16 + 8) * 36 + ac];
            a[mt][2] = As[(ar + mt * 16    ) * 36 + ac + 4];
            a[mt][3] = As[(ar + mt * 16 + 8) * 36 + ac + 4];
        }
        const int bk = kk * 8 + (lane & 3);
        const int bn = wn * 32 + (lane >> 2);
        unsigned b[4][2];
        #pragma unroll
        for (int nt = 0; nt < 4; ++nt) {
            b[nt][0] = Bs[bk * 72 + bn + nt * 8];
            b[nt][1] = Bs[(bk + 4) * 72 + bn + nt * 8];
        }
        #pragma unroll
        for (int mt = 0; mt < 2; ++mt)
            #pragma unroll
            for (int nt = 0; nt < 4; ++nt)
                mma8(acc[mt][nt], a[mt][0], a[mt][1], a[mt][2], a[mt][3],
                     b[nt][0], b[nt][1]);
    }
}

// QKV projection: grid (64, H, 3). Q/K stored e-interleaved; V transposed,
// s-interleaved. All values tf32-rounded (consumed raw by attn).
__global__ void __launch_bounds__(256, 4) qkv_gemm(
    const float* __restrict__ bQ, const float* __restrict__ bK, const float* __restrict__ bV,
    float* __restrict__ q, float* __restrict__ k, float* __restrict__ vt)
{
    extern __shared__ unsigned sm[];
    const int row0 = blockIdx.x * 128;
    const int h    = blockIdx.y;
    const int m    = blockIdx.z;
    const int tid  = threadIdx.x;
    const int lane = tid & 31;
    const int wid  = tid >> 5;
    const int wm   = wid >> 1, wn = wid & 1;

    const float* Asrc = g_xt + (size_t)row0 * D_;
    const float* W    = (m == 0 ? g_wqr : m == 1 ? g_wkr : g_wvr) + (size_t)h * D_ * E_;
    const float* bias = m == 0 ? bQ : m == 1 ? bK : bV;

    float acc[2][4][4] = {};

    g_tile_ca(sm, 0, Asrc, W, E_, tid, 0);
    CP_COMMIT();
    for (int t = 0; t < 24; ++t) {
        if (t + 1 < 24) {
            g_tile_ca(sm, (t + 1) & 1, Asrc, W, E_, tid, (t + 1) * 32);
            CP_COMMIT();
            CP_WAIT1();
        } else {
            CP_WAIT0();
        }
        __syncthreads();
        g_compute(sm, t & 1, wm, wn, lane, acc);
        __syncthreads();
    }

    const int w0 = 2 * (lane & 3);         // e within 8-group (even)
    const int p0 = perm8(w0);
    const int p1 = perm8(w0 + 1);

    if (m < 2) {
        float* out = m == 0 ? q : k;
        #pragma unroll
        for (int mt = 0; mt < 2; ++mt) {
            #pragma unroll
            for (int rr = 0; rr < 2; ++rr) {
                int row = row0 + wm * 32 + mt * 16 + (lane >> 2) + rr * 8;
                int b_  = row / S_, s = row % S_;
                float* orow = out + ((size_t)(b_ * H_ + h) * S_ + s) * E_;
                #pragma unroll
                for (int nt = 0; nt < 4; ++nt) {
                    int eg = wn * 32 + nt * 8;
                    orow[eg + p0] = __uint_as_float(tf32cvt(acc[mt][nt][rr * 2    ] + bias[h * E_ + eg + w0]));
                    orow[eg + p1] = __uint_as_float(tf32cvt(acc[mt][nt][rr * 2 + 1] + bias[h * E_ + eg + w0 + 1]));
                }
            }
        }
    } else {
        // V transposed: vt[(b*H+h)*E + e][s-interleaved]
        #pragma unroll
        for (int mt = 0; mt < 2; ++mt) {
            #pragma unroll
            for (int rr = 0; rr < 2; ++rr) {
                int row = row0 + wm * 32 + mt * 16 + (lane >> 2) + rr * 8;
                int b_  = row / S_, s = row % S_;
                int spos = (s & ~7) + perm8(s & 7);
                #pragma unroll
                for (int nt = 0; nt < 4; ++nt) {
                    int e0 = wn * 32 + nt * 8 + w0;
                    vt[((size_t)(b_ * H_ + h) * E_ + e0    ) * S_ + spos] =
                        __uint_as_float(tf32cvt(acc[mt][nt][rr * 2    ] + bias[h * E_ + e0]));
                    vt[((size_t)(b_ * H_ + h) * E_ + e0 + 1) * S_ + spos] =
                        __uint_as_float(tf32cvt(acc[mt][nt][rr * 2 + 1] + bias[h * E_ + e0 + 1]));
                }
            }
        }
    }
}

// Output projection: grid (64, 12), unchanged from round 14.
__global__ void __launch_bounds__(256, 4) out_proj(
    const float* __restrict__ bO, float* __restrict__ out)
{
    extern __shared__ unsigned sm[];
    const int row0 = blockIdx.x * 128;
    const int n0   = blockIdx.y * 64;
    const int tid  = threadIdx.x;
    const int lane = tid & 31;
    const int wid  = tid >> 5;
    const int wm   = wid >> 1, wn = wid & 1;

    const float* Asrc = g_z + (size_t)row0 * D_;
    const float* Bsrc = g_wor + n0;

    float acc[2][4][4] = {};

    g_tile_ca(sm, 0, Asrc, Bsrc, D_, tid, 0);
    CP_COMMIT();
    for (int t = 0; t < 24; ++t) {
        if (t + 1 < 24) {
            g_tile_ca(sm, (t + 1) & 1, Asrc, Bsrc, D_, tid, (t + 1) * 32);
            CP_COMMIT();
            CP_WAIT1();
        } else {
            CP_WAIT0();
        }
        __syncthreads();
        g_compute(sm, t & 1, wm, wn, lane, acc);
        __syncthreads();
    }

    #pragma unroll
    for (int mt = 0; mt < 2; ++mt) {
        #pragma unroll
        for (int rr = 0; rr < 2; ++rr) {
            int row = row0 + wm * 32 + mt * 16 + (lane >> 2) + rr * 8;
            #pragma unroll
            for (int nt = 0; nt < 4; ++nt) {
                int d = n0 + wn * 32 + nt * 8 + 2 * (lane & 3);
                out[(size_t)row * D_ + d    ] = acc[mt][nt][rr * 2    ] + bO[d];
                out[(size_t)row * D_ + d + 1] = acc[mt][nt][rr * 2 + 1] + bO[d + 1];
            }
        }
    }
}

// ---------------------------------------------------------------------------
// Flash attention. Interleaved tiles, stride 72 words (conflict-free LDS.64):
//   Qs[64][72] (e-interleaved), KPs[64][72] (K tile, then P), Vs[64][72] (Vt).
// ---------------------------------------------------------------------------
#define ST_W  72
#define ST_U2 36
#define AT_SMEM 55296

__global__ void __launch_bounds__(128, 4) attn_kernel()
{
    extern __shared__ unsigned sm_u[];
    unsigned* Qs  = sm_u;                 // words
    unsigned* KPs = sm_u + 64 * ST_W;
    unsigned* Vs  = sm_u + 128 * ST_W;
    const uint2* Q2 = reinterpret_cast<const uint2*>(Qs);
    const uint2* K2 = reinterpret_cast<const uint2*>(KPs);
    const uint2* V2 = reinterpret_cast<const uint2*>(Vs);

    const int qt  = blockIdx.x;
    const int h   = blockIdx.y;
    const int b   = blockIdx.z;
    const int tid = threadIdx.x;
    const int lane = tid & 31;
    const int w    = tid >> 5;

    const size_t bh  = ((size_t)(b * H_ + h)) * S_ * E_;   // q/k base
    const size_t bhv = ((size_t)(b * H_ + h)) * E_ * S_;   // vt base

    // Q tile via cp.async
    #pragma unroll
    for (int i = 0; i < 8; ++i) {
        int idx = tid + i * 128;
        int r = idx >> 4, c4 = (idx & 15) * 4;
        cp16(smem_u32(&Qs[r * ST_W + c4]),
             &g_q[bh + (size_t)(qt * 64 + r) * E_ + c4]);
    }
    CP_COMMIT(); CP_WAIT0();
    __syncthreads();

    float o[8][4] = {};
    float m_[2] = { -1e30f, -1e30f };
    float l_[2] = { 0.f, 0.f };

    const int ar = w * 16 + (lane >> 2);
    const int lc = lane & 3;
    const float scale = 0.125f;

    const int w0 = 2 * lc;
    const int pp0 = perm8(w0);
    const int pp1 = perm8(w0 + 1);

    for (int jt = 0; jt <= qt; ++jt) {
        // K tile [key][e-int], V tile [e][key-int] via cp.async
        #pragma unroll
        for (int i = 0; i < 8; ++i) {
            int idx = tid + i * 128;
            int r = idx >> 4, c4 = (idx & 15) * 4;
            cp16(smem_u32(&KPs[r * ST_W + c4]),
                 &g_k[bh + (size_t)(jt * 64 + r) * E_ + c4]);
            cp16(smem_u32(&Vs[r * ST_W + c4]),
                 &g_vt[bhv + (size_t)r * S_ + jt * 64 + c4]);
        }
        CP_COMMIT(); CP_WAIT0();
        __syncthreads();

        // S = Q K^T  (LDS.64 fragments)
        float s[8][4] = {};
        #pragma unroll
        for (int kk = 0; kk < 8; ++kk) {
            int qi = ar * ST_U2 + kk * 4 + lc;
            uint2 qa = Q2[qi];
            uint2 qb = Q2[qi + 8 * ST_U2];
            #pragma unroll
            for (int nt = 0; nt < 8; ++nt) {
                uint2 bk = K2[(nt * 8 + (lane >> 2)) * ST_U2 + kk * 4 + lc];
                mma8(s[nt], qa.x, qb.x, qa.y, qb.y, bk.x, bk.y);
            }
        }

        // scale + causal mask + online softmax
        const int qrow0 = qt * 64 + w * 16 + (lane >> 2);
        float mnew0 = m_[0], mnew1 = m_[1];
        #pragma unroll
        for (int nt = 0; nt < 8; ++nt) {
            int col = jt * 64 + nt * 8 + w0;
            float v0 = s[nt][0] * scale;
            float v1 = s[nt][1] * scale;
            float v2 = s[nt][2] * scale;
            float v3 = s[nt][3] * scale;
            if (jt == qt) {
                if (col     > qrow0)     v0 = -1e30f;
                if (col + 1 > qrow0)     v1 = -1e30f;
                if (col     > qrow0 + 8) v2 = -1e30f;
                if (col + 1 > qrow0 + 8) v3 = -1e30f;
            }
            s[nt][0] = v0; s[nt][1] = v1; s[nt][2] = v2; s[nt][3] = v3;
            mnew0 = fmaxf(mnew0, fmaxf(v0, v1));
            mnew1 = fmaxf(mnew1, fmaxf(v2, v3));
        }
        mnew0 = fmaxf(mnew0, __shfl_xor_sync(0xffffffffu, mnew0, 1));
        mnew0 = fmaxf(mnew0, __shfl_xor_sync(0xffffffffu, mnew0, 2));
        mnew1 = fmaxf(mnew1, __shfl_xor_sync(0xffffffffu, mnew1, 1));
        mnew1 = fmaxf(mnew1, __shfl_xor_sync(0xffffffffu, mnew1, 2));

        float f0 = __expf(m_[0] - mnew0);
        float f1 = __expf(m_[1] - mnew1);
        float sum0 = 0.f, sum1 = 0.f;
        #pragma unroll
        for (int nt = 0; nt < 8; ++nt) {
            s[nt][0] = __expf(s[nt][0] - mnew0);
            s[nt][1] = __expf(s[nt][1] - mnew0);
            s[nt][2] = __expf(s[nt][2] - mnew1);
            s[nt][3] = __expf(s[nt][3] - mnew1);
            sum0 += s[nt][0] + s[nt][1];
            sum1 += s[nt][2] + s[nt][3];
        }
        sum0 += __shfl_xor_sync(0xffffffffu, sum0, 1);
        sum0 += __shfl_xor_sync(0xffffffffu, sum0, 2);
        sum1 += __shfl_xor_sync(0xffffffffu, sum1, 1);
        sum1 += __shfl_xor_sync(0xffffffffu, sum1, 2);
        l_[0] = l_[0] * f0 + sum0;
        l_[1] = l_[1] * f1 + sum1;
        m_[0] = mnew0;
        m_[1] = mnew1;

        #pragma unroll
        for (int nt = 0; nt < 8; ++nt) {
            o[nt][0] *= f0; o[nt][1] *= f0;
            o[nt][2] *= f1; o[nt][3] *= f1;
        }

        // All warps must finish reading K before P overwrites the K tile
        __syncthreads();

        // store P interleaved into KPs
        {
            int pr = w * 16 + (lane >> 2);
            #pragma unroll
            for (int nt = 0; nt < 8; ++nt) {
                int base = nt * 8;
                KPs[(pr    ) * ST_W + base + pp0] = tf32cvt(s[nt][0]);
                KPs[(pr    ) * ST_W + base + pp1] = tf32cvt(s[nt][1]);
                KPs[(pr + 8) * ST_W + base + pp0] = tf32cvt(s[nt][2]);
                KPs[(pr + 8) * ST_W + base + pp1] = tf32cvt(s[nt][3]);
            }
        }
        __syncwarp();   // P@V reads only this warp's rows of KPs

        // O += P @ V  (LDS.64 fragments)
        #pragma unroll
        for (int kt = 0; kt < 8; ++kt) {
            int pi = ar * ST_U2 + kt * 4 + lc;
            uint2 pa = K2[pi];
            uint2 pb = K2[pi + 8 * ST_U2];
            #pragma unroll
            for (int nt = 0; nt < 8; ++nt) {
                uint2 bv = V2[(nt * 8 + (lane >> 2)) * ST_U2 + kt * 4 + lc];
                mma8(o[nt], pa.x, pb.x, pa.y, pb.y, bv.x, bv.y);
            }
        }
        __syncthreads();   // guard K/V reload and P overwrite next iter
    }

    // normalize + write z (tf32-rounded; out_proj consumes raw)
    float inv0 = 1.0f / l_[0];
    float inv1 = 1.0f / l_[1];
    int qr = qt * 64 + w * 16 + (lane >> 2);
    #pragma unroll
    for (int nt = 0; nt < 8; ++nt) {
        int e = nt * 8 + w0;
        size_t base0 = (size_t)(b * S_ + qr) * D_ + h * E_ + e;
        size_t base1 = (size_t)(b * S_ + qr + 8) * D_ + h * E_ + e;
        g_z[base0    ] = __uint_as_float(tf32cvt(o[nt][0] * inv0));
        g_z[base0 + 1] = __uint_as_float(tf32cvt(o[nt][1] * inv0));
        g_z[base1    ] = __uint_as_float(tf32cvt(o[nt][2] * inv1));
        g_z[base1 + 1] = __uint_as_float(tf32cvt(o[nt][3] * inv1));
    }
}

// ---------------------------------------------------------------------------
extern "C" void kernel_launch(void* const* d_in, const int* in_sizes, int n_in,
                              void* d_out, int out_size)
{
    const float* x  = (const float*)d_in[0];
    const float* WQ = (const float*)d_in[1];
    const float* WK = (const float*)d_in[2];
    const float* WV = (const float*)d_in[3];
    const float* WO = (const float*)d_in[4];
    const float* bQ = (const float*)d_in[5];
    const float* bK = (const float*)d_in[6];
    const float* bV = (const float*)d_in[7];
    const float* bO = (const float*)d_in[8];
    float* out = (float*)d_out;

    float *q, *k, *vt, *xt, *wqr, *wkr, *wvr, *wor;
    cudaGetSymbolAddress((void**)&q,   g_q);
    cudaGetSymbolAddress((void**)&k,   g_k);
    cudaGetSymbolAddress((void**)&vt,  g_vt);
    cudaGetSymbolAddress((void**)&xt,  g_xt);
    cudaGetSymbolAddress((void**)&wqr, g_wqr);
    cudaGetSymbolAddress((void**)&wkr, g_wkr);
    cudaGetSymbolAddress((void**)&wvr, g_wvr);
    cudaGetSymbolAddress((void**)&wor, g_wor);

    // Pre-round everything to tf32
    const int n4x = BS_ * D_ / 4;
    const int n4w = H_ * D_ * E_ / 4;
    const int n4o = D_ * D_ / 4;
    round_tf32<<<(n4x + 255) / 256, 256>>>(x,  xt,  n4x);
    round_tf32<<<(n4w + 255) / 256, 256>>>(WQ, wqr, n4w);
    round_tf32<<<(n4w + 255) / 256, 256>>>(WK, wkr, n4w);
    round_tf32<<<(n4w + 255) / 256, 256>>>(WV, wvr, n4w);
    round_tf32<<<(n4o + 255) / 256, 256>>>(WO, wor, n4o);

    // QKV projections (cp.async double-buffered)
    cudaFuncSetAttribute(qkv_gemm, cudaFuncAttributeMaxDynamicSharedMemorySize, G_SMEM_B);
    qkv_gemm<<<dim3(BS_ / 128, H_, 3), 256, G_SMEM_B>>>(bQ, bK, bV, q, k, vt);

    // Flash attention (interleaved LDS.64 fragments)
    cudaFuncSetAttribute(attn_kernel, cudaFuncAttributeMaxDynamicSharedMemorySize, AT_SMEM);
    attn_kernel<<<dim3(S_ / 64, H_, B_), 128, AT_SMEM>>>();

    // Output projection (cp.async double-buffered)
    cudaFuncSetAttribute(out_proj, cudaFuncAttributeMaxDynamicSharedMemorySize, G_SMEM_B);
    out_proj<<<dim3(BS_ / 128, D_ / 64), 256, G_SMEM_B>>>(bO, out);
}